// round 12
// baseline (speedup 1.0000x reference)
#include <cuda_runtime.h>
#include <cuda_fp16.h>
#include <stdint.h>

#define N_OUT  11008
#define K_TOT  4096
#define M_TOK  64
#define HIGH_K 1024
#define NT     64      // output columns per CTA
#define KC     64      // K per chunk
#define CPC    8       // chunks per CTA (split-K = 8)
#define NSPLIT 8
#define THREADS 384    // 4 consumer warps + 8 producer warps

// SMEM layout
//   A ring:   3 x 8192   @ 0       (fp16, pre-swizzled, consumer-staged)
//   B ring:   4 x 8192   @ 24576   (fp16, swizzled, producer-dequanted)
//   RAW ring: 3 x 12544  @ 57344   (packed W 12288 + scales 256)
//   mbar:     full[4], empty[4] @ 94976
#define ASTG  8192
#define BR0   24576
#define RAW0  57344
#define RAWST 12544
#define MBAR  94976
#define SMEM_BYTES 95040

__device__ __half g_xp[M_TOK * K_TOT];                    // permuted x fp16 (512KB)
__device__ float  g_part[(NSPLIT - 1) * M_TOK * N_OUT];   // split-K partials (19.7MB)

__device__ __forceinline__ uint32_t smem_u32(const void* p) {
    uint32_t a;
    asm("{ .reg .u64 t; cvta.to.shared.u64 t, %1; cvt.u32.u64 %0, t; }" : "=r"(a) : "l"(p));
    return a;
}
__device__ __forceinline__ uint32_t swz(uint32_t o) { return o ^ ((o >> 3) & 0x70); }

__device__ __forceinline__ void cp16(uint32_t dst, const void* src) {
    asm volatile("cp.async.cg.shared.global [%0], [%1], 16;" :: "r"(dst), "l"(src));
}
__device__ __forceinline__ void cp_commit() {
    asm volatile("cp.async.commit_group;" ::: "memory");
}
__device__ __forceinline__ void cp_wait1() {
    asm volatile("cp.async.wait_group 1;" ::: "memory");
}
__device__ __forceinline__ void cp_wait2g() {
    asm volatile("cp.async.wait_group 2;" ::: "memory");
}
__device__ __forceinline__ void prod_bar() {
    asm volatile("bar.sync 1, 256;" ::: "memory");   // producers (threads 128..383)
}
__device__ __forceinline__ void cons_bar() {
    asm volatile("bar.sync 2, 128;" ::: "memory");   // consumers (threads 0..127)
}

__device__ __forceinline__ void mbar_init(uint32_t addr, uint32_t cnt) {
    asm volatile("mbarrier.init.shared.b64 [%0], %1;" :: "r"(addr), "r"(cnt) : "memory");
}
__device__ __forceinline__ void mbar_arrive(uint32_t addr) {
    asm volatile("mbarrier.arrive.shared.b64 _, [%0];" :: "r"(addr) : "memory");
}
__device__ __forceinline__ void mbar_wait(uint32_t addr, uint32_t ph) {
    asm volatile(
        "{\n\t.reg .pred P;\n"
        "W_%=:\n\t"
        "mbarrier.try_wait.parity.acquire.cta.shared::cta.b64 P, [%0], %1, 0x989680;\n\t"
        "@!P bra W_%=;\n\t}"
        :: "r"(addr), "r"(ph) : "memory");
}

__device__ __forceinline__ void ldm_x4(uint32_t& r0, uint32_t& r1, uint32_t& r2, uint32_t& r3,
                                       uint32_t addr) {
    asm volatile("ldmatrix.sync.aligned.m8n8.x4.shared.b16 {%0,%1,%2,%3}, [%4];"
                 : "=r"(r0), "=r"(r1), "=r"(r2), "=r"(r3) : "r"(addr));
}
__device__ __forceinline__ void mma16816(float& c0, float& c1, float& c2, float& c3,
                                         uint32_t a0, uint32_t a1, uint32_t a2, uint32_t a3,
                                         uint32_t b0, uint32_t b1) {
    asm volatile("mma.sync.aligned.m16n8k16.row.col.f32.f16.f16.f32 "
                 "{%0,%1,%2,%3}, {%4,%5,%6,%7}, {%8,%9}, {%0,%1,%2,%3};"
                 : "+f"(c0), "+f"(c1), "+f"(c2), "+f"(c3)
                 : "r"(a0), "r"(a1), "r"(a2), "r"(a3), "r"(b0), "r"(b1));
}

// magic-number fp16 pair: u = 0x6400|v ; (u - off) * s
__device__ __forceinline__ uint32_t dq2(uint32_t bits, uint32_t off, uint32_t s2) {
    uint32_t u = 0x64006400u | bits;
    __half2 h = __hsub2(*reinterpret_cast<__half2*>(&u),
                        *reinterpret_cast<const __half2*>(&off));
    h = __hmul2(h, *reinterpret_cast<const __half2*>(&s2));
    return *reinterpret_cast<uint32_t*>(&h);
}

// ---------------- prep: x_perm -> fp16 (2 rows per thread, ci reuse) ----------------
__global__ void prep_kernel(const float* __restrict__ x, const int* __restrict__ ci) {
    int t = blockIdx.x * blockDim.x + threadIdx.x;   // 131072 threads
    int m = t >> 12;                                 // 0..31
    int k = t & 4095;
    int c = ci[k];
    g_xp[(m << 12) + k]        = __float2half_rn(x[(m << 12) + c]);
    g_xp[((m + 32) << 12) + k] = __float2half_rn(x[((m + 32) << 12) + c]);
}

// ---------------- reduce: out = out + 7 partials + bias ----------------
__global__ void reduce_kernel(float* __restrict__ out, const float* __restrict__ bias) {
    int n = blockIdx.x * blockDim.x + threadIdx.x;
    int m = blockIdx.y;
    int i = m * N_OUT + n;
    float s = out[i] + bias[n];
    #pragma unroll
    for (int j = 0; j < NSPLIT - 1; ++j)
        s += g_part[i + j * (M_TOK * N_OUT)];
    out[i] = s;
}

// ---------------- warp-specialized dequant + mma.sync GEMM (split-K 8) ----------------
__global__ void __launch_bounds__(THREADS, 2) gemm_kernel(
    const int* __restrict__ Wh, const int* __restrict__ Wl,
    const float* __restrict__ sh, const float* __restrict__ sl,
    float* __restrict__ out)
{
    extern __shared__ char smem[];
    const uint32_t sb = smem_u32(smem);
    const int tid = threadIdx.x;
    const int n0 = blockIdx.x * NT;
    const int kh = blockIdx.y;          // 0..7; kh<2 pure 6-bit, kh>=2 pure 5-bit
    const int cbase = kh * CPC;

    const int lane = tid & 31;
    const int wid  = tid >> 5;

    if (tid == 0) {
        #pragma unroll
        for (int s = 0; s < 4; ++s) {
            mbar_init(sb + MBAR + s * 8, 256);        // full[s]: producers
            mbar_init(sb + MBAR + 32 + s * 8, 128);   // empty[s]: consumers
        }
    }
    __syncthreads();

    if (wid < 4) {
        // ================= CONSUMER (threads 0..127), 32m x 32n per warp =================
        const int ctid = tid;
        const int wm = wid & 1;          // 32-row tile
        const int wn = wid >> 1;         // 32-col tile
        const int sub = lane >> 3;
        // A sub-tile t (t=0,1): rows wm*32 + t*16
        uint32_t offA[2], offB[2];
        #pragma unroll
        for (int t = 0; t < 2; ++t)
            offA[t] = (uint32_t)((wm * 32 + t * 16 + (sub & 1) * 8 + (lane & 7)) * 128 + (sub >> 1) * 16);
        #pragma unroll
        for (int u = 0; u < 2; ++u)
            offB[u] = (uint32_t)((wn * 32 + u * 16 + (sub >> 1) * 8 + (lane & 7)) * 128 + (sub & 1) * 16);

        // self-staged A ring (depth 3), 4 granules per thread
        auto issueA = [&](int cf) {
            const int k0 = (cbase + cf) * KC;
            const uint32_t slot = sb + (uint32_t)((cf % 3) * ASTG);
            #pragma unroll
            for (int j = 0; j < 4; ++j) {
                int g = ctid + j * 128;
                cp16(slot + swz((uint32_t)((g >> 3) * 128 + (g & 7) * 16)),
                     g_xp + ((g >> 3) << 12) + k0 + ((g & 7) << 3));
            }
        };

        float acc[2][4][4];
        #pragma unroll
        for (int t = 0; t < 2; ++t)
            #pragma unroll
            for (int j = 0; j < 4; ++j)
                #pragma unroll
                for (int i = 0; i < 4; ++i) acc[t][j][i] = 0.0f;

        issueA(0); cp_commit();
        issueA(1); cp_commit();

        for (int c = 0; c < CPC; ++c) {
            cons_bar();                       // all consumers done reading A[c-1]
            if (c + 2 < CPC) issueA(c + 2);   // overwrites A[(c-1)%3] post-bar
            cp_commit();
            cp_wait2g();                      // own A(c) granules done
            cons_bar();                       // cross-thread visibility of A[c]

            mbar_wait(sb + MBAR + (c & 3) * 8, (c >> 2) & 1);   // B full
            const uint32_t ab = sb + (uint32_t)((c % 3) * ASTG);
            const uint32_t bb = sb + BR0 + (uint32_t)((c & 3) * 8192);
            #pragma unroll
            for (int ks = 0; ks < 4; ++ks) {
                uint32_t a[2][4], b[2][4];
                #pragma unroll
                for (int t = 0; t < 2; ++t)
                    ldm_x4(a[t][0], a[t][1], a[t][2], a[t][3],
                           ab + swz(offA[t] + (uint32_t)(ks * 32)));
                #pragma unroll
                for (int u = 0; u < 2; ++u)
                    ldm_x4(b[u][0], b[u][1], b[u][2], b[u][3],
                           bb + swz(offB[u] + (uint32_t)(ks * 32)));
                #pragma unroll
                for (int t = 0; t < 2; ++t)
                    #pragma unroll
                    for (int u = 0; u < 2; ++u) {
                        mma16816(acc[t][2*u][0], acc[t][2*u][1], acc[t][2*u][2], acc[t][2*u][3],
                                 a[t][0], a[t][1], a[t][2], a[t][3], b[u][0], b[u][1]);
                        mma16816(acc[t][2*u+1][0], acc[t][2*u+1][1], acc[t][2*u+1][2], acc[t][2*u+1][3],
                                 a[t][0], a[t][1], a[t][2], a[t][3], b[u][2], b[u][3]);
                    }
            }
            mbar_arrive(sb + MBAR + 32 + (c & 3) * 8);          // B empty
        }

        // epilogue: kh=0 -> out, kh>=1 -> g_part[kh-1]
        float* dst = (kh == 0) ? out : (g_part + (kh - 1) * (M_TOK * N_OUT));
        #pragma unroll
        for (int t = 0; t < 2; ++t) {
            const int r0 = wm * 32 + t * 16 + (lane >> 2);
            #pragma unroll
            for (int j = 0; j < 4; ++j) {
                const int nb = n0 + wn * 32 + (j >> 1) * 16 + (j & 1) * 8 + (lane & 3) * 2;
                float2 o;
                o.x = acc[t][j][0];
                o.y = acc[t][j][1];
                *(float2*)(dst + r0 * N_OUT + nb) = o;
                o.x = acc[t][j][2];
                o.y = acc[t][j][3];
                *(float2*)(dst + (r0 + 8) * N_OUT + nb) = o;
            }
        }
    } else {
        // ================= PRODUCER (threads 128..383) =================
        const int ptid = tid - 128;     // 0..255
        const int c2 = ptid & 31;       // 2-col group: cols 2c2, 2c2+1
        const int qp = ptid >> 5;       // quad-pair (6b) / octet (5b), 0..7

        auto issueW = [&](int cf) {
            const int cg = cbase + cf;
            const int k0 = cg * KC;
            const uint32_t slot = sb + RAW0 + (uint32_t)((cf % 3) * RAWST);
            if (cg < 16) {
                const int* src = Wh + 48 * cg * N_OUT + n0;
                #pragma unroll
                for (int b = 0; b < 3; ++b) {
                    int g = ptid + b * 256;
                    cp16(slot + (g >> 4) * 256 + (g & 15) * 16,
                         src + (g >> 4) * N_OUT + (g & 15) * 4);
                }
                if (ptid < 16)
                    cp16(slot + 12288 + ptid * 16, sh + (k0 >> 7) * N_OUT + n0 + ptid * 4);
            } else {
                const int* src = Wl + 40 * (cg - 16) * N_OUT + n0;
                #pragma unroll
                for (int b = 0; b < 2; ++b) {
                    int g = ptid + b * 256;
                    cp16(slot + (g >> 4) * 256 + (g & 15) * 16,
                         src + (g >> 4) * N_OUT + (g & 15) * 4);
                }
                if (ptid < 128) {
                    int g = ptid + 512;
                    cp16(slot + (g >> 4) * 256 + (g & 15) * 16,
                         src + (g >> 4) * N_OUT + (g & 15) * 4);
                }
                if (ptid < 16)
                    cp16(slot + 12288 + ptid * 16,
                         sl + ((k0 - HIGH_K) >> 7) * N_OUT + n0 + ptid * 4);
            }
        };

        issueW(0); cp_commit();
        issueW(1); cp_commit();

        for (int c = 0; c < CPC; ++c) {
            cp_wait1();          // own W(c) group complete
            prod_bar();          // all producers: W(c) visible, dequant(c-1) finished
            if (c + 2 < CPC) issueW(c + 2);   // overwrites raw[(c-1)%3] post-bar
            cp_commit();

            const int cg = cbase + c;
            const char* rawp = smem + RAW0 + (c % 3) * RAWST;
            const float2 sc = *(const float2*)(rawp + 12288 + c2 * 8);
            const uint32_t bb = BR0 + (uint32_t)((c & 3) * 8192);

            mbar_wait(sb + MBAR + 32 + (c & 3) * 8, ((c >> 2) & 1) ^ 1);   // B empty

            if (cg < 16) {   // 6-bit: 2 cols x quads {2qp, 2qp+1}
                int2 r[6];
                #pragma unroll
                for (int j = 0; j < 6; ++j)
                    r[j] = *(const int2*)(rawp + (6 * qp + j) * 256 + c2 * 8);
                #pragma unroll
                for (int cc = 0; cc < 2; ++cc) {
                    const float sf = cc ? sc.y : sc.x;
                    const __half2 sh2v = __half2half2(__float2half_rn(sf));
                    const uint32_t s2 = *reinterpret_cast<const uint32_t*>(&sh2v);
                    int w0 = cc ? r[0].y : r[0].x;
                    int w1 = cc ? r[1].y : r[1].x;
                    int w2 = cc ? r[2].y : r[2].x;
                    int w3 = cc ? r[3].y : r[3].x;
                    int w4 = cc ? r[4].y : r[4].x;
                    int w5 = cc ? r[5].y : r[5].x;
                    uint4 val;
                    val.x = dq2((w0 & 63) | ((w0 & 0xC0) << 10) | ((w1 & 15) << 18), 0x641F641Fu, s2);
                    val.y = dq2(((w1 >> 4) & 15) | ((w2 & 3) << 4) | ((w2 & 0xFC) << 14), 0x641F641Fu, s2);
                    val.z = dq2((w3 & 63) | ((w3 & 0xC0) << 10) | ((w4 & 15) << 18), 0x641F641Fu, s2);
                    val.w = dq2(((w4 >> 4) & 15) | ((w5 & 3) << 4) | ((w5 & 0xFC) << 14), 0x641F641Fu, s2);
                    *(uint4*)(smem + bb + swz((uint32_t)((2 * c2 + cc) * 128 + qp * 16))) = val;
                }
            } else {         // 5-bit: 2 cols x octet qp
                int2 r[5];
                #pragma unroll
                for (int j = 0; j < 5; ++j)
                    r[j] = *(const int2*)(rawp + (5 * qp + j) * 256 + c2 * 8);
                #pragma unroll
                for (int cc = 0; cc < 2; ++cc) {
                    const float sf = cc ? sc.y : sc.x;
                    const __half2 sh2v = __half2half2(__float2half_rn(sf));
                    const uint32_t s2 = *reinterpret_cast<const uint32_t*>(&sh2v);
                    int w0 = cc ? r[0].y : r[0].x;
                    int w1 = cc ? r[1].y : r[1].x;
                    int w2 = cc ? r[2].y : r[2].x;
                    int w3 = cc ? r[3].y : r[3].x;
                    int w4 = cc ? r[4].y : r[4].x;
                    uint4 val;
                    val.x = dq2((w0 & 31) | ((w0 & 0xE0) << 11) | ((w1 & 3) << 19), 0x640F640Fu, s2);
                    val.y = dq2(((w1 >> 2) & 31) | ((w1 & 0x80) << 9) | ((w2 & 15) << 17), 0x640F640Fu, s2);
                    val.z = dq2(((w2 >> 4) & 15) | ((w3 & 1) << 4) | ((w3 & 0x3E) << 15), 0x640F640Fu, s2);
                    val.w = dq2(((w3 >> 6) & 3) | ((w4 & 7) << 2) | ((w4 & 0xF8) << 13), 0x640F640Fu, s2);
                    *(uint4*)(smem + bb + swz((uint32_t)((2 * c2 + cc) * 128 + qp * 16))) = val;
                }
            }
            mbar_arrive(sb + MBAR + (c & 3) * 8);     // B full
        }
    }
}

extern "C" void kernel_launch(void* const* d_in, const int* in_sizes, int n_in,
                              void* d_out, int out_size) {
    const float* x    = (const float*)d_in[0];
    const int*   Wh   = (const int*)d_in[1];
    const int*   Wl   = (const int*)d_in[2];
    const float* sh   = (const float*)d_in[3];
    const float* sl   = (const float*)d_in[4];
    const int*   ci   = (const int*)d_in[5];
    const float* bias = (const float*)d_in[6];
    float* out = (float*)d_out;

    cudaFuncSetAttribute(gemm_kernel, cudaFuncAttributeMaxDynamicSharedMemorySize, SMEM_BYTES);

    prep_kernel<<<(M_TOK / 2 * K_TOT) / 256, 256>>>(x, ci);
    gemm_kernel<<<dim3(N_OUT / NT, NSPLIT), THREADS, SMEM_BYTES>>>(Wh, Wl, sh, sl, out);
    reduce_kernel<<<dim3(N_OUT / 256, M_TOK), 256>>>(out, bias);
}

// round 13
// speedup vs baseline: 1.0160x; 1.0160x over previous
#include <cuda_runtime.h>
#include <cuda_fp16.h>
#include <stdint.h>

#define N_OUT  11008
#define K_TOT  4096
#define M_TOK  64
#define HIGH_K 1024
#define NT     64      // output columns per CTA
#define KC     64      // K per chunk
#define CPC    16      // chunks per CTA (split-K = 4)
#define NSPLIT 4
#define THREADS 384    // 4 consumer warps + 8 producer warps

// SMEM layout
//   A ring:   6 x 8192   @ 0       (fp16, pre-swizzled, per-warp consumer-staged)
//   B ring:   3 x 8192   @ 49152   (fp16, swizzled, producer-dequanted)
//   RAW ring: 3 x 12544  @ 73728   (packed W 12288 + scales 256)
//   mbar:     full[3], empty[3] @ 111360
#define ASTG  8192
#define BR0   49152
#define RAW0  73728
#define RAWST 12544
#define MBAR  111360
#define SMEM_BYTES 111616

__device__ __half g_xp[M_TOK * K_TOT];                    // permuted x fp16 (512KB)
__device__ float  g_part[(NSPLIT - 1) * M_TOK * N_OUT];   // split-K partials (8.4MB)

__device__ __forceinline__ uint32_t smem_u32(const void* p) {
    uint32_t a;
    asm("{ .reg .u64 t; cvta.to.shared.u64 t, %1; cvt.u32.u64 %0, t; }" : "=r"(a) : "l"(p));
    return a;
}
__device__ __forceinline__ uint32_t swz(uint32_t o) { return o ^ ((o >> 3) & 0x70); }

__device__ __forceinline__ void cp16(uint32_t dst, const void* src) {
    asm volatile("cp.async.cg.shared.global [%0], [%1], 16;" :: "r"(dst), "l"(src));
}
__device__ __forceinline__ void cp_commit() {
    asm volatile("cp.async.commit_group;" ::: "memory");
}
__device__ __forceinline__ void cp_wait1() {
    asm volatile("cp.async.wait_group 1;" ::: "memory");
}
__device__ __forceinline__ void cp_wait2g() {
    asm volatile("cp.async.wait_group 2;" ::: "memory");
}
__device__ __forceinline__ void prod_bar() {
    asm volatile("bar.sync 1, 256;" ::: "memory");   // producers (threads 128..383)
}

__device__ __forceinline__ void mbar_init(uint32_t addr, uint32_t cnt) {
    asm volatile("mbarrier.init.shared.b64 [%0], %1;" :: "r"(addr), "r"(cnt) : "memory");
}
__device__ __forceinline__ void mbar_arrive(uint32_t addr) {
    asm volatile("mbarrier.arrive.shared.b64 _, [%0];" :: "r"(addr) : "memory");
}
__device__ __forceinline__ void mbar_wait(uint32_t addr, uint32_t ph) {
    asm volatile(
        "{\n\t.reg .pred P;\n"
        "W_%=:\n\t"
        "mbarrier.try_wait.parity.acquire.cta.shared::cta.b64 P, [%0], %1, 0x989680;\n\t"
        "@!P bra W_%=;\n\t}"
        :: "r"(addr), "r"(ph) : "memory");
}

__device__ __forceinline__ void ldm_x4(uint32_t& r0, uint32_t& r1, uint32_t& r2, uint32_t& r3,
                                       uint32_t addr) {
    asm volatile("ldmatrix.sync.aligned.m8n8.x4.shared.b16 {%0,%1,%2,%3}, [%4];"
                 : "=r"(r0), "=r"(r1), "=r"(r2), "=r"(r3) : "r"(addr));
}
__device__ __forceinline__ void mma16816(float& c0, float& c1, float& c2, float& c3,
                                         uint32_t a0, uint32_t a1, uint32_t a2, uint32_t a3,
                                         uint32_t b0, uint32_t b1) {
    asm volatile("mma.sync.aligned.m16n8k16.row.col.f32.f16.f16.f32 "
                 "{%0,%1,%2,%3}, {%4,%5,%6,%7}, {%8,%9}, {%0,%1,%2,%3};"
                 : "+f"(c0), "+f"(c1), "+f"(c2), "+f"(c3)
                 : "r"(a0), "r"(a1), "r"(a2), "r"(a3), "r"(b0), "r"(b1));
}

// magic-number fp16 pair: u = 0x6400|v ; (u - off) * s
__device__ __forceinline__ uint32_t dq2(uint32_t bits, uint32_t off, uint32_t s2) {
    uint32_t u = 0x64006400u | bits;
    __half2 h = __hsub2(*reinterpret_cast<__half2*>(&u),
                        *reinterpret_cast<const __half2*>(&off));
    h = __hmul2(h, *reinterpret_cast<const __half2*>(&s2));
    return *reinterpret_cast<uint32_t*>(&h);
}

// ---------------- prep: x_perm -> fp16 (2 rows per thread, ci reuse) ----------------
__global__ void prep_kernel(const float* __restrict__ x, const int* __restrict__ ci) {
    int t = blockIdx.x * blockDim.x + threadIdx.x;   // 131072 threads
    int m = t >> 12;                                 // 0..31
    int k = t & 4095;
    int c = ci[k];
    g_xp[(m << 12) + k]        = __float2half_rn(x[(m << 12) + c]);
    g_xp[((m + 32) << 12) + k] = __float2half_rn(x[((m + 32) << 12) + c]);
}

// ---------------- reduce: out = out + 3 partials + bias ----------------
__global__ void reduce_kernel(float* __restrict__ out, const float* __restrict__ bias) {
    int n = blockIdx.x * blockDim.x + threadIdx.x;
    int m = blockIdx.y;
    int i = m * N_OUT + n;
    out[i] = out[i] + g_part[i] + g_part[i + M_TOK * N_OUT]
                    + g_part[i + 2 * (M_TOK * N_OUT)] + bias[n];
}

// ---------------- warp-specialized dequant + mma.sync GEMM (split-K 4) ----------------
__global__ void __launch_bounds__(THREADS, 2) gemm_kernel(
    const int* __restrict__ Wh, const int* __restrict__ Wl,
    const float* __restrict__ sh, const float* __restrict__ sl,
    float* __restrict__ out)
{
    extern __shared__ char smem[];
    const uint32_t sb = smem_u32(smem);
    const int tid = threadIdx.x;
    const int n0 = blockIdx.x * NT;
    const int kh = blockIdx.y;          // 0..3
    const int cbase = kh * CPC;

    const int lane = tid & 31;
    const int wid  = tid >> 5;

    if (tid == 0) {
        #pragma unroll
        for (int s = 0; s < 3; ++s) {
            mbar_init(sb + MBAR + s * 8, 256);        // full[s]: producers
            mbar_init(sb + MBAR + 24 + s * 8, 128);   // empty[s]: consumers
        }
    }
    __syncthreads();

    if (wid < 4) {
        // ========== CONSUMER (threads 0..127), 32m x 32n per warp, barrier-free ==========
        const int wm = wid & 1;          // 32-row tile
        const int wn = wid >> 1;         // 32-col tile
        const int sub = lane >> 3;
        uint32_t offA[2], offB[2];
        #pragma unroll
        for (int t = 0; t < 2; ++t)
            offA[t] = (uint32_t)((wm * 32 + t * 16 + (sub & 1) * 8 + (lane & 7)) * 128 + (sub >> 1) * 16);
        #pragma unroll
        for (int u = 0; u < 2; ++u)
            offB[u] = (uint32_t)((wn * 32 + u * 16 + (sub >> 1) * 8 + (lane & 7)) * 128 + (sub & 1) * 16);

        // Per-warp A staging: warp stages its OWN 32 m-rows (partner warp writes
        // byte-identical duplicates — benign). Visibility: wait_group + syncwarp.
        auto issueA = [&](int cf) {
            const int k0 = (cbase + cf) * KC;
            const uint32_t slot = sb + (uint32_t)((cf % 6) * ASTG);
            #pragma unroll
            for (int j = 0; j < 8; ++j) {
                int gi = j * 32 + lane;              // 0..255
                int row = wm * 32 + (gi >> 3);       // m row this warp owns
                int kb = gi & 7;
                cp16(slot + swz((uint32_t)(row * 128 + kb * 16)),
                     g_xp + (row << 12) + k0 + (kb << 3));
            }
        };

        float acc[2][4][4];
        #pragma unroll
        for (int t = 0; t < 2; ++t)
            #pragma unroll
            for (int j = 0; j < 4; ++j)
                #pragma unroll
                for (int i = 0; i < 4; ++i) acc[t][j][i] = 0.0f;

        issueA(0); cp_commit();
        issueA(1); cp_commit();

        for (int c = 0; c < CPC; ++c) {
            if (c + 2 < CPC) issueA(c + 2);   // slot (c+2)%6: reuse-safe (skew<=2, dist>=4)
            cp_commit();
            cp_wait2g();                      // own A(c) copies complete
            __syncwarp();                     // publish across lanes (no cross-warp bar!)

            mbar_wait(sb + MBAR + (c % 3) * 8, (c / 3) & 1);   // B full
            const uint32_t ab = sb + (uint32_t)((c % 6) * ASTG);
            const uint32_t bb = sb + BR0 + (uint32_t)((c % 3) * 8192);
            #pragma unroll
            for (int ks = 0; ks < 4; ++ks) {
                uint32_t a[2][4], b[2][4];
                #pragma unroll
                for (int t = 0; t < 2; ++t)
                    ldm_x4(a[t][0], a[t][1], a[t][2], a[t][3],
                           ab + swz(offA[t] + (uint32_t)(ks * 32)));
                #pragma unroll
                for (int u = 0; u < 2; ++u)
                    ldm_x4(b[u][0], b[u][1], b[u][2], b[u][3],
                           bb + swz(offB[u] + (uint32_t)(ks * 32)));
                #pragma unroll
                for (int t = 0; t < 2; ++t)
                    #pragma unroll
                    for (int u = 0; u < 2; ++u) {
                        mma16816(acc[t][2*u][0], acc[t][2*u][1], acc[t][2*u][2], acc[t][2*u][3],
                                 a[t][0], a[t][1], a[t][2], a[t][3], b[u][0], b[u][1]);
                        mma16816(acc[t][2*u+1][0], acc[t][2*u+1][1], acc[t][2*u+1][2], acc[t][2*u+1][3],
                                 a[t][0], a[t][1], a[t][2], a[t][3], b[u][2], b[u][3]);
                    }
            }
            mbar_arrive(sb + MBAR + 24 + (c % 3) * 8);          // B empty
        }

        // epilogue: kh=0 -> out, kh>=1 -> g_part[kh-1]
        float* dst = (kh == 0) ? out : (g_part + (kh - 1) * (M_TOK * N_OUT));
        #pragma unroll
        for (int t = 0; t < 2; ++t) {
            const int r0 = wm * 32 + t * 16 + (lane >> 2);
            #pragma unroll
            for (int j = 0; j < 4; ++j) {
                const int nb = n0 + wn * 32 + (j >> 1) * 16 + (j & 1) * 8 + (lane & 3) * 2;
                float2 o;
                o.x = acc[t][j][0];
                o.y = acc[t][j][1];
                *(float2*)(dst + r0 * N_OUT + nb) = o;
                o.x = acc[t][j][2];
                o.y = acc[t][j][3];
                *(float2*)(dst + (r0 + 8) * N_OUT + nb) = o;
            }
        }
    } else {
        // ================= PRODUCER (threads 128..383) =================
        const int ptid = tid - 128;     // 0..255
        const int c2 = ptid & 31;       // 2-col group: cols 2c2, 2c2+1
        const int qp = ptid >> 5;       // quad-pair (6b) / octet (5b), 0..7

        auto issueW = [&](int cf) {
            const int cg = cbase + cf;
            const int k0 = cg * KC;
            const uint32_t slot = sb + RAW0 + (uint32_t)((cf % 3) * RAWST);
            if (cg < 16) {
                const int* src = Wh + 48 * cg * N_OUT + n0;
                #pragma unroll
                for (int b = 0; b < 3; ++b) {
                    int g = ptid + b * 256;
                    cp16(slot + (g >> 4) * 256 + (g & 15) * 16,
                         src + (g >> 4) * N_OUT + (g & 15) * 4);
                }
                if (ptid < 16)
                    cp16(slot + 12288 + ptid * 16, sh + (k0 >> 7) * N_OUT + n0 + ptid * 4);
            } else {
                const int* src = Wl + 40 * (cg - 16) * N_OUT + n0;
                #pragma unroll
                for (int b = 0; b < 2; ++b) {
                    int g = ptid + b * 256;
                    cp16(slot + (g >> 4) * 256 + (g & 15) * 16,
                         src + (g >> 4) * N_OUT + (g & 15) * 4);
                }
                if (ptid < 128) {
                    int g = ptid + 512;
                    cp16(slot + (g >> 4) * 256 + (g & 15) * 16,
                         src + (g >> 4) * N_OUT + (g & 15) * 4);
                }
                if (ptid < 16)
                    cp16(slot + 12288 + ptid * 16,
                         sl + ((k0 - HIGH_K) >> 7) * N_OUT + n0 + ptid * 4);
            }
        };

        issueW(0); cp_commit();
        issueW(1); cp_commit();

        for (int c = 0; c < CPC; ++c) {
            cp_wait1();          // own W(c) group complete
            prod_bar();          // all producers: W(c) visible, dequant(c-1) finished
            if (c + 2 < CPC) issueW(c + 2);   // overwrites raw[(c-1)%3] post-bar
            cp_commit();

            const int cg = cbase + c;
            const char* rawp = smem + RAW0 + (c % 3) * RAWST;
            const float2 sc = *(const float2*)(rawp + 12288 + c2 * 8);
            const uint32_t bb = BR0 + (uint32_t)((c % 3) * 8192);

            mbar_wait(sb + MBAR + 24 + (c % 3) * 8, ((c / 3) & 1) ^ 1);   // B empty

            if (cg < 16) {   // 6-bit: 2 cols x quads {2qp, 2qp+1}
                int2 r[6];
                #pragma unroll
                for (int j = 0; j < 6; ++j)
                    r[j] = *(const int2*)(rawp + (6 * qp + j) * 256 + c2 * 8);
                #pragma unroll
                for (int cc = 0; cc < 2; ++cc) {
                    const float sf = cc ? sc.y : sc.x;
                    const __half2 sh2v = __half2half2(__float2half_rn(sf));
                    const uint32_t s2 = *reinterpret_cast<const uint32_t*>(&sh2v);
                    int w0 = cc ? r[0].y : r[0].x;
                    int w1 = cc ? r[1].y : r[1].x;
                    int w2 = cc ? r[2].y : r[2].x;
                    int w3 = cc ? r[3].y : r[3].x;
                    int w4 = cc ? r[4].y : r[4].x;
                    int w5 = cc ? r[5].y : r[5].x;
                    uint4 val;
                    val.x = dq2((w0 & 63) | ((w0 & 0xC0) << 10) | ((w1 & 15) << 18), 0x641F641Fu, s2);
                    val.y = dq2(((w1 >> 4) & 15) | ((w2 & 3) << 4) | ((w2 & 0xFC) << 14), 0x641F641Fu, s2);
                    val.z = dq2((w3 & 63) | ((w3 & 0xC0) << 10) | ((w4 & 15) << 18), 0x641F641Fu, s2);
                    val.w = dq2(((w4 >> 4) & 15) | ((w5 & 3) << 4) | ((w5 & 0xFC) << 14), 0x641F641Fu, s2);
                    *(uint4*)(smem + bb + swz((uint32_t)((2 * c2 + cc) * 128 + qp * 16))) = val;
                }
            } else {         // 5-bit: 2 cols x octet qp
                int2 r[5];
                #pragma unroll
                for (int j = 0; j < 5; ++j)
                    r[j] = *(const int2*)(rawp + (5 * qp + j) * 256 + c2 * 8);
                #pragma unroll
                for (int cc = 0; cc < 2; ++cc) {
                    const float sf = cc ? sc.y : sc.x;
                    const __half2 sh2v = __half2half2(__float2half_rn(sf));
                    const uint32_t s2 = *reinterpret_cast<const uint32_t*>(&sh2v);
                    int w0 = cc ? r[0].y : r[0].x;
                    int w1 = cc ? r[1].y : r[1].x;
                    int w2 = cc ? r[2].y : r[2].x;
                    int w3 = cc ? r[3].y : r[3].x;
                    int w4 = cc ? r[4].y : r[4].x;
                    uint4 val;
                    val.x = dq2((w0 & 31) | ((w0 & 0xE0) << 11) | ((w1 & 3) << 19), 0x640F640Fu, s2);
                    val.y = dq2(((w1 >> 2) & 31) | ((w1 & 0x80) << 9) | ((w2 & 15) << 17), 0x640F640Fu, s2);
                    val.z = dq2(((w2 >> 4) & 15) | ((w3 & 1) << 4) | ((w3 & 0x3E) << 15), 0x640F640Fu, s2);
                    val.w = dq2(((w3 >> 6) & 3) | ((w4 & 7) << 2) | ((w4 & 0xF8) << 13), 0x640F640Fu, s2);
                    *(uint4*)(smem + bb + swz((uint32_t)((2 * c2 + cc) * 128 + qp * 16))) = val;
                }
            }
            mbar_arrive(sb + MBAR + (c % 3) * 8);     // B full
        }
    }
}

extern "C" void kernel_launch(void* const* d_in, const int* in_sizes, int n_in,
                              void* d_out, int out_size) {
    const float* x    = (const float*)d_in[0];
    const int*   Wh   = (const int*)d_in[1];
    const int*   Wl   = (const int*)d_in[2];
    const float* sh   = (const float*)d_in[3];
    const float* sl   = (const float*)d_in[4];
    const int*   ci   = (const int*)d_in[5];
    const float* bias = (const float*)d_in[6];
    float* out = (float*)d_out;

    cudaFuncSetAttribute(gemm_kernel, cudaFuncAttributeMaxDynamicSharedMemorySize, SMEM_BYTES);

    prep_kernel<<<(M_TOK / 2 * K_TOT) / 256, 256>>>(x, ci);
    gemm_kernel<<<dim3(N_OUT / NT, NSPLIT), THREADS, SMEM_BYTES>>>(Wh, Wl, sh, sl, out);
    reduce_kernel<<<dim3(N_OUT / 256, M_TOK), 256>>>(out, bias);
}

// round 14
// speedup vs baseline: 1.1030x; 1.0856x over previous
#include <cuda_runtime.h>
#include <cuda_fp16.h>
#include <stdint.h>

#define N_OUT  11008
#define K_TOT  4096
#define M_TOK  64
#define HIGH_K 1024
#define NT     64      // output columns per CTA
#define KC     64      // K per chunk
#define CPC    16      // chunks per CTA (split-K = 4)
#define NSPLIT 4
#define THREADS 384    // 4 consumer warps + 8 producer warps

// SMEM layout
//   A ring: 6 x 8192 @ 0      (fp16, pre-swizzled, per-warp consumer-staged)
//   B ring: 4 x 8192 @ 49152  (fp16, swizzled, producer-dequanted from GMEM regs)
//   mbar:   full[4], empty[4] @ 81920
#define ASTG  8192
#define BR0   49152
#define MBAR  81920
#define SMEM_BYTES 82176

__device__ __half g_xp[M_TOK * K_TOT];                    // permuted x fp16 (512KB)
__device__ float  g_part[(NSPLIT - 1) * M_TOK * N_OUT];   // split-K partials (8.4MB)

__device__ __forceinline__ uint32_t smem_u32(const void* p) {
    uint32_t a;
    asm("{ .reg .u64 t; cvta.to.shared.u64 t, %1; cvt.u32.u64 %0, t; }" : "=r"(a) : "l"(p));
    return a;
}
__device__ __forceinline__ uint32_t swz(uint32_t o) { return o ^ ((o >> 3) & 0x70); }

__device__ __forceinline__ void cp16(uint32_t dst, const void* src) {
    asm volatile("cp.async.cg.shared.global [%0], [%1], 16;" :: "r"(dst), "l"(src));
}
__device__ __forceinline__ void cp_commit() {
    asm volatile("cp.async.commit_group;" ::: "memory");
}
__device__ __forceinline__ void cp_wait2g() {
    asm volatile("cp.async.wait_group 2;" ::: "memory");
}

__device__ __forceinline__ void mbar_init(uint32_t addr, uint32_t cnt) {
    asm volatile("mbarrier.init.shared.b64 [%0], %1;" :: "r"(addr), "r"(cnt) : "memory");
}
__device__ __forceinline__ void mbar_arrive(uint32_t addr) {
    asm volatile("mbarrier.arrive.shared.b64 _, [%0];" :: "r"(addr) : "memory");
}
__device__ __forceinline__ void mbar_wait(uint32_t addr, uint32_t ph) {
    asm volatile(
        "{\n\t.reg .pred P;\n"
        "W_%=:\n\t"
        "mbarrier.try_wait.parity.acquire.cta.shared::cta.b64 P, [%0], %1, 0x989680;\n\t"
        "@!P bra W_%=;\n\t}"
        :: "r"(addr), "r"(ph) : "memory");
}

__device__ __forceinline__ void ldm_x4(uint32_t& r0, uint32_t& r1, uint32_t& r2, uint32_t& r3,
                                       uint32_t addr) {
    asm volatile("ldmatrix.sync.aligned.m8n8.x4.shared.b16 {%0,%1,%2,%3}, [%4];"
                 : "=r"(r0), "=r"(r1), "=r"(r2), "=r"(r3) : "r"(addr));
}
__device__ __forceinline__ void mma16816(float& c0, float& c1, float& c2, float& c3,
                                         uint32_t a0, uint32_t a1, uint32_t a2, uint32_t a3,
                                         uint32_t b0, uint32_t b1) {
    asm volatile("mma.sync.aligned.m16n8k16.row.col.f32.f16.f16.f32 "
                 "{%0,%1,%2,%3}, {%4,%5,%6,%7}, {%8,%9}, {%0,%1,%2,%3};"
                 : "+f"(c0), "+f"(c1), "+f"(c2), "+f"(c3)
                 : "r"(a0), "r"(a1), "r"(a2), "r"(a3), "r"(b0), "r"(b1));
}

// magic-number fp16 pair: u = 0x6400|v ; (u - off) * s
__device__ __forceinline__ uint32_t dq2(uint32_t bits, uint32_t off, uint32_t s2) {
    uint32_t u = 0x64006400u | bits;
    __half2 h = __hsub2(*reinterpret_cast<__half2*>(&u),
                        *reinterpret_cast<const __half2*>(&off));
    h = __hmul2(h, *reinterpret_cast<const __half2*>(&s2));
    return *reinterpret_cast<uint32_t*>(&h);
}

// ---------------- prep: x_perm -> fp16 (2 rows per thread, ci reuse) ----------------
__global__ void prep_kernel(const float* __restrict__ x, const int* __restrict__ ci) {
    int t = blockIdx.x * blockDim.x + threadIdx.x;   // 131072 threads
    int m = t >> 12;                                 // 0..31
    int k = t & 4095;
    int c = ci[k];
    g_xp[(m << 12) + k]        = __float2half_rn(x[(m << 12) + c]);
    g_xp[((m + 32) << 12) + k] = __float2half_rn(x[((m + 32) << 12) + c]);
}

// ---------------- reduce: out = out + 3 partials + bias ----------------
__global__ void reduce_kernel(float* __restrict__ out, const float* __restrict__ bias) {
    int n = blockIdx.x * blockDim.x + threadIdx.x;
    int m = blockIdx.y;
    int i = m * N_OUT + n;
    out[i] = out[i] + g_part[i] + g_part[i + M_TOK * N_OUT]
                    + g_part[i + 2 * (M_TOK * N_OUT)] + bias[n];
}

// ---------------- warp-specialized dequant + mma.sync GEMM (split-K 4) ----------------
__global__ void __launch_bounds__(THREADS, 2) gemm_kernel(
    const int* __restrict__ Wh, const int* __restrict__ Wl,
    const float* __restrict__ sh, const float* __restrict__ sl,
    float* __restrict__ out)
{
    extern __shared__ char smem[];
    const uint32_t sb = smem_u32(smem);
    const int tid = threadIdx.x;
    const int n0 = blockIdx.x * NT;
    const int kh = blockIdx.y;          // 0: pure 6-bit; 1..3: pure 5-bit
    const int cbase = kh * CPC;

    const int lane = tid & 31;
    const int wid  = tid >> 5;

    if (tid == 0) {
        #pragma unroll
        for (int s = 0; s < 4; ++s) {
            mbar_init(sb + MBAR + s * 8, 256);        // full[s]: producer threads
            mbar_init(sb + MBAR + 32 + s * 8, 128);   // empty[s]: consumer threads
        }
    }
    __syncthreads();

    if (wid < 4) {
        // ========== CONSUMER (threads 0..127), 32m x 32n per warp, barrier-free ==========
        const int wm = wid & 1;
        const int wn = wid >> 1;
        const int sub = lane >> 3;
        uint32_t offA[2], offB[2];
        #pragma unroll
        for (int t = 0; t < 2; ++t)
            offA[t] = (uint32_t)((wm * 32 + t * 16 + (sub & 1) * 8 + (lane & 7)) * 128 + (sub >> 1) * 16);
        #pragma unroll
        for (int u = 0; u < 2; ++u)
            offB[u] = (uint32_t)((wn * 32 + u * 16 + (sub >> 1) * 8 + (lane & 7)) * 128 + (sub & 1) * 16);

        // Per-warp A staging (duplicates with partner warp — benign identical bytes)
        auto issueA = [&](int cf) {
            const int k0 = (cbase + cf) * KC;
            const uint32_t slot = sb + (uint32_t)((cf % 6) * ASTG);
            #pragma unroll
            for (int j = 0; j < 8; ++j) {
                int gi = j * 32 + lane;
                int row = wm * 32 + (gi >> 3);
                int kb = gi & 7;
                cp16(slot + swz((uint32_t)(row * 128 + kb * 16)),
                     g_xp + (row << 12) + k0 + (kb << 3));
            }
        };

        float acc[2][4][4];
        #pragma unroll
        for (int t = 0; t < 2; ++t)
            #pragma unroll
            for (int j = 0; j < 4; ++j)
                #pragma unroll
                for (int i = 0; i < 4; ++i) acc[t][j][i] = 0.0f;

        issueA(0); cp_commit();
        issueA(1); cp_commit();

        for (int c = 0; c < CPC; ++c) {
            if (c + 2 < CPC) issueA(c + 2);   // slot (c+2)%6: safe (skew<=3, reuse dist 6)
            cp_commit();
            cp_wait2g();                      // own A(c) copies complete
            __syncwarp();                     // publish across lanes

            mbar_wait(sb + MBAR + (c & 3) * 8, (c >> 2) & 1);   // B full
            const uint32_t ab = sb + (uint32_t)((c % 6) * ASTG);
            const uint32_t bb = sb + BR0 + (uint32_t)((c & 3) * 8192);
            #pragma unroll
            for (int ks = 0; ks < 4; ++ks) {
                uint32_t a[2][4], b[2][4];
                #pragma unroll
                for (int t = 0; t < 2; ++t)
                    ldm_x4(a[t][0], a[t][1], a[t][2], a[t][3],
                           ab + swz(offA[t] + (uint32_t)(ks * 32)));
                #pragma unroll
                for (int u = 0; u < 2; ++u)
                    ldm_x4(b[u][0], b[u][1], b[u][2], b[u][3],
                           bb + swz(offB[u] + (uint32_t)(ks * 32)));
                #pragma unroll
                for (int t = 0; t < 2; ++t)
                    #pragma unroll
                    for (int u = 0; u < 2; ++u) {
                        mma16816(acc[t][2*u][0], acc[t][2*u][1], acc[t][2*u][2], acc[t][2*u][3],
                                 a[t][0], a[t][1], a[t][2], a[t][3], b[u][0], b[u][1]);
                        mma16816(acc[t][2*u+1][0], acc[t][2*u+1][1], acc[t][2*u+1][2], acc[t][2*u+1][3],
                                 a[t][0], a[t][1], a[t][2], a[t][3], b[u][2], b[u][3]);
                    }
            }
            mbar_arrive(sb + MBAR + 32 + (c & 3) * 8);          // B empty
        }

        // epilogue: kh=0 -> out, kh>=1 -> g_part[kh-1]
        float* dst = (kh == 0) ? out : (g_part + (kh - 1) * (M_TOK * N_OUT));
        #pragma unroll
        for (int t = 0; t < 2; ++t) {
            const int r0 = wm * 32 + t * 16 + (lane >> 2);
            #pragma unroll
            for (int j = 0; j < 4; ++j) {
                const int nb = n0 + wn * 32 + (j >> 1) * 16 + (j & 1) * 8 + (lane & 3) * 2;
                float2 o;
                o.x = acc[t][j][0];
                o.y = acc[t][j][1];
                *(float2*)(dst + r0 * N_OUT + nb) = o;
                o.x = acc[t][j][2];
                o.y = acc[t][j][3];
                *(float2*)(dst + (r0 + 8) * N_OUT + nb) = o;
            }
        }
    } else {
        // ===== PRODUCER (threads 128..383): dequant straight from GMEM registers =====
        // Warp qp owns packed rows [R*qp, R*qp+R) of each chunk, all 64 columns.
        // Thread (lane) owns columns {c2, c2+32}; LDGs are fully coalesced.
        const int c2 = lane;
        const int qp = wid - 4;         // 0..7

        if (kh == 0) {
            // ---------- 6-bit region: 12 W words + 2 scales per thread ----------
            auto ld6 = [&](int c, int* w, float& s0, float& s1) {
                const int cg = cbase + c;
                const int* src = Wh + 48 * cg * N_OUT + n0;
                #pragma unroll
                for (int j = 0; j < 6; ++j) {
                    w[j]     = src[(6 * qp + j) * N_OUT + c2];
                    w[6 + j] = src[(6 * qp + j) * N_OUT + c2 + 32];
                }
                s0 = sh[(cg >> 1) * N_OUT + n0 + c2];
                s1 = sh[(cg >> 1) * N_OUT + n0 + c2 + 32];
            };
            int wc[12]; float s0c, s1c;
            ld6(0, wc, s0c, s1c);
            #pragma unroll 2
            for (int c = 0; c < CPC; ++c) {
                int wn_[12]; float s0n = 0.f, s1n = 0.f;
                if (c + 1 < CPC) ld6(c + 1, wn_, s0n, s1n);
                mbar_wait(sb + MBAR + 32 + (c & 3) * 8, ((c >> 2) & 1) ^ 1);   // B empty
                const uint32_t bb = BR0 + (uint32_t)((c & 3) * 8192);
                #pragma unroll
                for (int cc = 0; cc < 2; ++cc) {
                    const int* w = wc + 6 * cc;
                    const float sf = cc ? s1c : s0c;
                    const __half2 sh2v = __half2half2(__float2half_rn(sf));
                    const uint32_t s2 = *reinterpret_cast<const uint32_t*>(&sh2v);
                    uint4 val;
                    val.x = dq2((w[0] & 63) | ((w[0] & 0xC0) << 10) | ((w[1] & 15) << 18), 0x641F641Fu, s2);
                    val.y = dq2(((w[1] >> 4) & 15) | ((w[2] & 3) << 4) | ((w[2] & 0xFC) << 14), 0x641F641Fu, s2);
                    val.z = dq2((w[3] & 63) | ((w[3] & 0xC0) << 10) | ((w[4] & 15) << 18), 0x641F641Fu, s2);
                    val.w = dq2(((w[4] >> 4) & 15) | ((w[5] & 3) << 4) | ((w[5] & 0xFC) << 14), 0x641F641Fu, s2);
                    *(uint4*)(smem + bb + swz((uint32_t)((c2 + 32 * cc) * 128 + qp * 16))) = val;
                }
                mbar_arrive(sb + MBAR + (c & 3) * 8);     // B full
                #pragma unroll
                for (int j = 0; j < 12; ++j) wc[j] = wn_[j];
                s0c = s0n; s1c = s1n;
            }
        } else {
            // ---------- 5-bit region: 10 W words + 2 scales per thread ----------
            auto ld5 = [&](int c, int* w, float& s0, float& s1) {
                const int cg = cbase + c;
                const int* src = Wl + 40 * (cg - 16) * N_OUT + n0;
                #pragma unroll
                for (int j = 0; j < 5; ++j) {
                    w[j]     = src[(5 * qp + j) * N_OUT + c2];
                    w[5 + j] = src[(5 * qp + j) * N_OUT + c2 + 32];
                }
                s0 = sl[((cg - 16) >> 1) * N_OUT + n0 + c2];
                s1 = sl[((cg - 16) >> 1) * N_OUT + n0 + c2 + 32];
            };
            int wc[10]; float s0c, s1c;
            ld5(0, wc, s0c, s1c);
            #pragma unroll 2
            for (int c = 0; c < CPC; ++c) {
                int wn_[10]; float s0n = 0.f, s1n = 0.f;
                if (c + 1 < CPC) ld5(c + 1, wn_, s0n, s1n);
                mbar_wait(sb + MBAR + 32 + (c & 3) * 8, ((c >> 2) & 1) ^ 1);   // B empty
                const uint32_t bb = BR0 + (uint32_t)((c & 3) * 8192);
                #pragma unroll
                for (int cc = 0; cc < 2; ++cc) {
                    const int* w = wc + 5 * cc;
                    const float sf = cc ? s1c : s0c;
                    const __half2 sh2v = __half2half2(__float2half_rn(sf));
                    const uint32_t s2 = *reinterpret_cast<const uint32_t*>(&sh2v);
                    uint4 val;
                    val.x = dq2((w[0] & 31) | ((w[0] & 0xE0) << 11) | ((w[1] & 3) << 19), 0x640F640Fu, s2);
                    val.y = dq2(((w[1] >> 2) & 31) | ((w[1] & 0x80) << 9) | ((w[2] & 15) << 17), 0x640F640Fu, s2);
                    val.z = dq2(((w[2] >> 4) & 15) | ((w[3] & 1) << 4) | ((w[3] & 0x3E) << 15), 0x640F640Fu, s2);
                    val.w = dq2(((w[3] >> 6) & 3) | ((w[4] & 7) << 2) | ((w[4] & 0xF8) << 13), 0x640F640Fu, s2);
                    *(uint4*)(smem + bb + swz((uint32_t)((c2 + 32 * cc) * 128 + qp * 16))) = val;
                }
                mbar_arrive(sb + MBAR + (c & 3) * 8);     // B full
                #pragma unroll
                for (int j = 0; j < 10; ++j) wc[j] = wn_[j];
                s0c = s0n; s1c = s1n;
            }
        }
    }
}

extern "C" void kernel_launch(void* const* d_in, const int* in_sizes, int n_in,
                              void* d_out, int out_size) {
    const float* x    = (const float*)d_in[0];
    const int*   Wh   = (const int*)d_in[1];
    const int*   Wl   = (const int*)d_in[2];
    const float* sh   = (const float*)d_in[3];
    const float* sl   = (const float*)d_in[4];
    const int*   ci   = (const int*)d_in[5];
    const float* bias = (const float*)d_in[6];
    float* out = (float*)d_out;

    cudaFuncSetAttribute(gemm_kernel, cudaFuncAttributeMaxDynamicSharedMemorySize, SMEM_BYTES);

    prep_kernel<<<(M_TOK / 2 * K_TOT) / 256, 256>>>(x, ci);
    gemm_kernel<<<dim3(N_OUT / NT, NSPLIT), THREADS, SMEM_BYTES>>>(Wh, Wl, sh, sl, out);
    reduce_kernel<<<dim3(N_OUT / 256, M_TOK), 256>>>(out, bias);
}